// round 2
// baseline (speedup 1.0000x reference)
#include <cuda_runtime.h>
#include <cuda_bf16.h>
#include <math.h>

// ---------------- scratch (static device globals; no allocation) ----------------
__device__ float g_lbuf[256 * 22 * 4096];   // log-eig planes, layout [n][ch][pos]
__device__ float g_h2[256 * 32 * 4096];     // h2, layout [n][ch][pos]
__device__ float g_eusum[256 * 22];
__device__ float g_eusq[256 * 22];
__device__ float g_h2sum[256 * 32];
__device__ float g_h2sq[256 * 32];
__device__ float g_cov3[256 * 32];
__device__ float g_em3[10];

#define NSWEEPS 8

// round-robin pairing: round r in [0,63), pair k in [0,32)
__device__ __forceinline__ void pairpq(int r, int k, int& p, int& q) {
    if (k == 0) { p = 63; q = r; }
    else {
        p = r + k; if (p >= 63) p -= 63;
        q = r - k; if (q < 0)  q += 63;
    }
}

// ---------------- K0: init accumulators + scalar-embedding MLP ----------------
__global__ void init_kernel(const void* __restrict__ Mraw,
                            const float* __restrict__ we1, const float* __restrict__ be1,
                            const float* __restrict__ we2, const float* __restrict__ be2,
                            const float* __restrict__ we3, const float* __restrict__ be3,
                            const float* __restrict__ ln_g, const float* __restrict__ ln_b) {
    const int t = threadIdx.x;  // 256 threads, 1 block
    for (int i = t; i < 256 * 32; i += 256) {
        g_h2sum[i] = 0.f; g_h2sq[i] = 0.f; g_cov3[i] = 0.f;
    }
    __shared__ float md[2];
    __shared__ float em[10], emln[10], em2[100];
    __shared__ float mu_s, isd_s;
    if (t == 0) {
        int mi = *(const int*)Mraw;
        float Mv = (mi > 0 && mi < 100000000) ? (float)mi : __int_as_float(mi);
        md[0] = Mv / 500.0f;
        md[1] = 64.0f / 100.0f;
    }
    __syncthreads();
    if (t < 10) em[t] = md[0] * we1[t] + md[1] * we1[10 + t] + be1[t];
    __syncthreads();
    if (t == 0) {
        float s = 0.f, s2 = 0.f;
        for (int j = 0; j < 10; ++j) { s += em[j]; s2 += em[j] * em[j]; }
        float mu = s * 0.1f;
        float var = fmaxf(s2 * 0.1f - mu * mu, 0.f);
        mu_s = mu;
        isd_s = rsqrtf(var + 1e-3f);   // keras LN: eps inside sqrt
    }
    __syncthreads();
    if (t < 10) emln[t] = (em[t] - mu_s) * isd_s * ln_g[t] + ln_b[t];
    __syncthreads();
    if (t < 100) {
        float a = be2[t];
        for (int j = 0; j < 10; ++j) a += emln[j] * we2[j * 100 + t];
        em2[t] = fmaxf(a, 0.f);
    }
    __syncthreads();
    if (t < 10) {
        float a = be3[t];
        for (int k = 0; k < 100; ++k) a += em2[k] * we3[k * 10 + t];
        g_em3[t] = em[t] + a;
    }
}

// ---------------- K1: per-matrix Jacobi eig + log reconstruction ----------------
__global__ __launch_bounds__(128) void eig_kernel(const float* __restrict__ x) {
    __shared__ float A[64][65];
    __shared__ float V[64][65];
    __shared__ float cs[32], sn[32];
    __shared__ float fv[64];
    __shared__ float red[8];

    const int t = threadIdx.x;     // 0..127
    const int b = blockIdx.x;      // n*22 + ch
    const float* src = x + (size_t)b * 4096;

    // load raw plane
    #pragma unroll 4
    for (int it = 0; it < 32; ++it) {
        int id = t + 128 * it;
        A[id >> 6][id & 63] = src[id];
    }
    __syncthreads();
    // symmetrize + V = I
    #pragma unroll 4
    for (int it = 0; it < 32; ++it) {
        int id = t + 128 * it;
        int i = id >> 6, j = id & 63;
        if (i < j) {
            float a = 0.5f * (A[i][j] + A[j][i]);
            A[i][j] = a; A[j][i] = a;
        }
        V[i][j] = (i == j) ? 1.f : 0.f;
    }
    __syncthreads();

    for (int sweep = 0; sweep < NSWEEPS; ++sweep) {
        for (int r = 0; r < 63; ++r) {
            if (t < 32) {
                int p, q; pairpq(r, t, p, q);
                float app = A[p][p], aqq = A[q][q], apq = A[p][q];
                float c = 1.f, s = 0.f;
                float thr = 1e-7f * (fabsf(app) + fabsf(aqq)) + 1e-12f;
                if (fabsf(apq) > thr) {
                    float tau = (aqq - app) / (2.f * apq);
                    float tt = copysignf(1.f, tau) / (fabsf(tau) + sqrtf(1.f + tau * tau));
                    c = rsqrtf(1.f + tt * tt);
                    s = tt * c;
                }
                cs[t] = c; sn[t] = s;
            }
            __syncthreads();
            // column phase: A <- A*J ; V <- V*J
            #pragma unroll 2
            for (int it = 0; it < 16; ++it) {
                int id = t + 128 * it;          // 0..2047
                int k = id & 31, i = id >> 5;
                float s = sn[k];
                if (s != 0.f) {
                    float c = cs[k];
                    int p, q; pairpq(r, k, p, q);
                    float a0 = A[i][p], a1 = A[i][q];
                    A[i][p] = c * a0 - s * a1;
                    A[i][q] = s * a0 + c * a1;
                    float v0 = V[i][p], v1 = V[i][q];
                    V[i][p] = c * v0 - s * v1;
                    V[i][q] = s * v0 + c * v1;
                }
            }
            __syncthreads();
            // row phase: A <- J^T * A
            #pragma unroll 2
            for (int it = 0; it < 16; ++it) {
                int id = t + 128 * it;
                int k = id & 31, j = id >> 5;
                float s = sn[k];
                if (s != 0.f) {
                    float c = cs[k];
                    int p, q; pairpq(r, k, p, q);
                    float a0 = A[p][j], a1 = A[q][j];
                    A[p][j] = c * a0 - s * a1;
                    A[q][j] = s * a0 + c * a1;
                }
            }
            __syncthreads();
        }
    }

    // eigenvalues -> f(lambda)
    if (t < 64) fv[t] = logf(fmaxf(A[t][t], 1e-4f));
    __syncthreads();
    // W = V * diag(f), stored into A
    #pragma unroll 4
    for (int it = 0; it < 32; ++it) {
        int id = t + 128 * it;
        int i = id >> 6, m = id & 63;
        A[i][m] = V[i][m] * fv[m];
    }
    __syncthreads();
    // L[i][j] = sum_m W[i][m] * V[j][m]; write + accumulate stats
    float lsum = 0.f, lsq = 0.f;
    float* dst = g_lbuf + (size_t)b * 4096;
    for (int it = 0; it < 32; ++it) {
        int id = t + 128 * it;
        int i = id >> 6, j = id & 63;
        float acc = 0.f;
        #pragma unroll
        for (int m = 0; m < 64; ++m) acc += A[i][m] * V[j][m];
        dst[id] = acc;
        lsum += acc;
        lsq += acc * acc;
    }
    // block reduce
    #pragma unroll
    for (int off = 16; off; off >>= 1) {
        lsum += __shfl_down_sync(0xffffffffu, lsum, off);
        lsq  += __shfl_down_sync(0xffffffffu, lsq, off);
    }
    if ((t & 31) == 0) { red[t >> 5] = lsum; red[4 + (t >> 5)] = lsq; }
    __syncthreads();
    if (t == 0) {
        g_eusum[b] = red[0] + red[1] + red[2] + red[3];
        g_eusq[b]  = red[4] + red[5] + red[6] + red[7];
    }
}

// ---------------- K2: block 1  (matnorm(eu) @ w2 -> relu -> @w3 + eu) ----------------
__global__ __launch_bounds__(128) void dense1_kernel(const float* __restrict__ w2, const float* __restrict__ b2,
                                                     const float* __restrict__ w3, const float* __restrict__ b3) {
    const int t = threadIdx.x;
    const int n = blockIdx.y;
    const int pos = blockIdx.x * 128 + t;
    __shared__ float sw2[1024], sw3[1024], sb2[32], sb3[32];
    __shared__ float meanS[22], isdS[22], em3S[10];
    __shared__ float acc1[32], acc2[32];
    for (int i = t; i < 1024; i += 128) { sw2[i] = w2[i]; sw3[i] = w3[i]; }
    if (t < 32) { sb2[t] = b2[t]; sb3[t] = b3[t]; acc1[t] = 0.f; acc2[t] = 0.f; }
    if (t < 22) {
        float mu = g_eusum[n * 22 + t] * (1.f / 4096.f);
        float var = fmaxf(g_eusq[n * 22 + t] * (1.f / 4096.f) - mu * mu, 0.f);
        meanS[t] = mu;
        isdS[t] = 1.f / fmaxf(sqrtf(var), 1e-3f);   // matnorm: clamp OUTSIDE sqrt
    }
    if (t < 10) em3S[t] = g_em3[t];
    __syncthreads();

    float eu[32];
    #pragma unroll
    for (int c = 0; c < 22; ++c) eu[c] = g_lbuf[((size_t)n * 22 + c) * 4096 + pos];
    #pragma unroll
    for (int c = 22; c < 32; ++c) eu[c] = em3S[c - 22];
    float mt[22];
    #pragma unroll
    for (int c = 0; c < 22; ++c) mt[c] = (eu[c] - meanS[c]) * isdS[c];
    // matnorm of the constant embedding channels is exactly 0 (std clamped), so skip c>=22
    float res[32];
    #pragma unroll
    for (int o = 0; o < 32; ++o) {
        float a = sb2[o];
        #pragma unroll
        for (int c = 0; c < 22; ++c) a += mt[c] * sw2[c * 32 + o];
        res[o] = fmaxf(a, 0.f);
    }
    #pragma unroll
    for (int o = 0; o < 32; ++o) {
        float a = sb3[o];
        #pragma unroll
        for (int c = 0; c < 32; ++c) a += res[c] * sw3[c * 32 + o];
        float h = eu[o] + a;
        g_h2[((size_t)n * 32 + o) * 4096 + pos] = h;
        float s1 = h, s2 = h * h;
        #pragma unroll
        for (int off = 16; off; off >>= 1) {
            s1 += __shfl_down_sync(0xffffffffu, s1, off);
            s2 += __shfl_down_sync(0xffffffffu, s2, off);
        }
        if ((t & 31) == 0) { atomicAdd(&acc1[o], s1); atomicAdd(&acc2[o], s2); }
    }
    __syncthreads();
    if (t < 32) {
        atomicAdd(&g_h2sum[n * 32 + t], acc1[t]);
        atomicAdd(&g_h2sq[n * 32 + t], acc2[t]);
    }
}

// ---------------- K3: block 2  (matnorm(h2) @ w4 -> relu -> @w5 + h2, mean) ----------------
__global__ __launch_bounds__(128) void dense2_kernel(const float* __restrict__ w4, const float* __restrict__ b4,
                                                     const float* __restrict__ w5, const float* __restrict__ b5) {
    const int t = threadIdx.x;
    const int n = blockIdx.y;
    const int pos = blockIdx.x * 128 + t;
    __shared__ float sw4[1024], sw5[1024], sb4[32], sb5[32];
    __shared__ float meanS[32], isdS[32];
    __shared__ float acc1[32];
    for (int i = t; i < 1024; i += 128) { sw4[i] = w4[i]; sw5[i] = w5[i]; }
    if (t < 32) {
        sb4[t] = b4[t]; sb5[t] = b5[t]; acc1[t] = 0.f;
        float mu = g_h2sum[n * 32 + t] * (1.f / 4096.f);
        float var = fmaxf(g_h2sq[n * 32 + t] * (1.f / 4096.f) - mu * mu, 0.f);
        meanS[t] = mu;
        isdS[t] = 1.f / fmaxf(sqrtf(var), 1e-3f);
    }
    __syncthreads();

    float hv[32];
    #pragma unroll
    for (int c = 0; c < 32; ++c) hv[c] = g_h2[((size_t)n * 32 + c) * 4096 + pos];
    float mt[32];
    #pragma unroll
    for (int c = 0; c < 32; ++c) mt[c] = (hv[c] - meanS[c]) * isdS[c];
    float res[32];
    #pragma unroll
    for (int o = 0; o < 32; ++o) {
        float a = sb4[o];
        #pragma unroll
        for (int c = 0; c < 32; ++c) a += mt[c] * sw4[c * 32 + o];
        res[o] = fmaxf(a, 0.f);
    }
    #pragma unroll
    for (int o = 0; o < 32; ++o) {
        float a = sb5[o];
        #pragma unroll
        for (int c = 0; c < 32; ++c) a += res[c] * sw5[c * 32 + o];
        float h = hv[o] + a;
        float s1 = h;
        #pragma unroll
        for (int off = 16; off; off >>= 1) s1 += __shfl_down_sync(0xffffffffu, s1, off);
        if ((t & 31) == 0) atomicAdd(&acc1[o], s1);
    }
    __syncthreads();
    if (t < 32) atomicAdd(&g_cov3[n * 32 + t], acc1[t]);
}

// ---------------- K4: head (cov3 @ w -> softmax) ----------------
__global__ void head_kernel(const float* __restrict__ w, float* __restrict__ out) {
    const int n = threadIdx.x;  // 256 threads
    float c[32];
    #pragma unroll
    for (int ch = 0; ch < 32; ++ch) c[ch] = g_cov3[n * 32 + ch] * (1.f / 4096.f);
    float lg[7];
    #pragma unroll
    for (int cls = 0; cls < 7; ++cls) {
        float a = 0.f;
        #pragma unroll
        for (int ch = 0; ch < 32; ++ch) a += c[ch] * w[ch * 7 + cls];
        lg[cls] = a;
    }
    float mx = lg[0];
    #pragma unroll
    for (int cls = 1; cls < 7; ++cls) mx = fmaxf(mx, lg[cls]);
    float sum = 0.f;
    #pragma unroll
    for (int cls = 0; cls < 7; ++cls) { lg[cls] = expf(lg[cls] - mx); sum += lg[cls]; }
    float inv = 1.f / sum;
    #pragma unroll
    for (int cls = 0; cls < 7; ++cls) out[n * 7 + cls] = lg[cls] * inv;
}

// ---------------- launch ----------------
extern "C" void kernel_launch(void* const* d_in, const int* in_sizes, int n_in,
                              void* d_out, int out_size) {
    const float* x   = (const float*)d_in[0];
    const void*  M   = d_in[1];
    const float* w   = (const float*)d_in[2];
    const float* w2  = (const float*)d_in[3];
    const float* b2  = (const float*)d_in[4];
    const float* w3  = (const float*)d_in[5];
    const float* b3  = (const float*)d_in[6];
    const float* w4  = (const float*)d_in[7];
    const float* b4  = (const float*)d_in[8];
    const float* w5  = (const float*)d_in[9];
    const float* b5  = (const float*)d_in[10];
    const float* we1 = (const float*)d_in[11];
    const float* be1 = (const float*)d_in[12];
    const float* we2 = (const float*)d_in[13];
    const float* be2 = (const float*)d_in[14];
    const float* we3 = (const float*)d_in[15];
    const float* be3 = (const float*)d_in[16];
    const float* lng = (const float*)d_in[17];
    const float* lnb = (const float*)d_in[18];

    init_kernel<<<1, 256>>>(M, we1, be1, we2, be2, we3, be3, lng, lnb);
    eig_kernel<<<256 * 22, 128>>>(x);
    dense1_kernel<<<dim3(32, 256), 128>>>(w2, b2, w3, b3);
    dense2_kernel<<<dim3(32, 256), 128>>>(w4, b4, w5, b5);
    head_kernel<<<1, 256>>>(w, (float*)d_out);
}

// round 4
// speedup vs baseline: 1.3411x; 1.3411x over previous
#include <cuda_runtime.h>
#include <cuda_bf16.h>
#include <math.h>

// ---------------- scratch (static device globals; no allocation) ----------------
__device__ float g_lbuf[256 * 22 * 4096];   // log-eig planes, layout [n][ch][pos]
__device__ float g_h2[256 * 32 * 4096];     // h2, layout [n][ch][pos]
__device__ float g_eusum[256 * 22];
__device__ float g_eusq[256 * 22];
__device__ float g_h2sum[256 * 32];
__device__ float g_h2sq[256 * 32];
__device__ float g_cov3[256 * 32];
__device__ float g_em3[10];

#define MAXSWEEPS 10

// round-robin pairing: round r in [0,63), pair k in [0,32)
__device__ __forceinline__ void pairpq(int r, int k, int& p, int& q) {
    if (k == 0) { p = 63; q = r; }
    else {
        p = r + k; if (p >= 63) p -= 63;
        q = r - k; if (q < 0)  q += 63;
    }
}

// ---------------- K0: init accumulators + scalar-embedding MLP ----------------
__global__ void init_kernel(const void* __restrict__ Mraw,
                            const float* __restrict__ we1, const float* __restrict__ be1,
                            const float* __restrict__ we2, const float* __restrict__ be2,
                            const float* __restrict__ we3, const float* __restrict__ be3,
                            const float* __restrict__ ln_g, const float* __restrict__ ln_b) {
    const int t = threadIdx.x;  // 256 threads, 1 block
    for (int i = t; i < 256 * 32; i += 256) {
        g_h2sum[i] = 0.f; g_h2sq[i] = 0.f; g_cov3[i] = 0.f;
    }
    __shared__ float md[2];
    __shared__ float em[10], emln[10], em2[100];
    __shared__ float mu_s, isd_s;
    if (t == 0) {
        int mi = *(const int*)Mraw;
        float Mv = (mi > 0 && mi < 100000000) ? (float)mi : __int_as_float(mi);
        md[0] = Mv / 500.0f;
        md[1] = 64.0f / 100.0f;
    }
    __syncthreads();
    if (t < 10) em[t] = md[0] * we1[t] + md[1] * we1[10 + t] + be1[t];
    __syncthreads();
    if (t == 0) {
        float s = 0.f, s2 = 0.f;
        for (int j = 0; j < 10; ++j) { s += em[j]; s2 += em[j] * em[j]; }
        float mu = s * 0.1f;
        float var = fmaxf(s2 * 0.1f - mu * mu, 0.f);
        mu_s = mu;
        isd_s = rsqrtf(var + 1e-3f);   // keras LN: eps inside sqrt
    }
    __syncthreads();
    if (t < 10) emln[t] = (em[t] - mu_s) * isd_s * ln_g[t] + ln_b[t];
    __syncthreads();
    if (t < 100) {
        float a = be2[t];
        for (int j = 0; j < 10; ++j) a += emln[j] * we2[j * 100 + t];
        em2[t] = fmaxf(a, 0.f);
    }
    __syncthreads();
    if (t < 10) {
        float a = be3[t];
        for (int k = 0; k < 100; ++k) a += em2[k] * we3[k * 10 + t];
        g_em3[t] = em[t] + a;
    }
}

// ---------------- K1: per-matrix Jacobi eig + log reconstruction ----------------
// 256 threads = 8 warps. Warp w owns pairs 4w..4w+3 in each phase, so the
// rotation-skip test is warp-uniform and all smem accesses are conflict-free.
__global__ __launch_bounds__(256, 5) void eig_kernel(const float* __restrict__ x) {
    __shared__ float A[64][65];
    __shared__ float V[64][65];
    __shared__ float cs[32], sn[32];
    __shared__ float fv[64];
    __shared__ float wred[16];
    __shared__ float anorm_s;
    __shared__ int conv_s;

    const int t = threadIdx.x;
    const int warp = t >> 5, lane = t & 31;
    const int b = blockIdx.x;      // n*22 + ch
    const float* src = x + (size_t)b * 4096;

    // load raw plane (16 elems/thread, coalesced)
    #pragma unroll
    for (int it = 0; it < 16; ++it) {
        int id = t + 256 * it;
        A[id >> 6][id & 63] = src[id];
    }
    __syncthreads();
    // symmetrize + V = I + infinity-norm scale
    float amax = 0.f;
    #pragma unroll
    for (int it = 0; it < 16; ++it) {
        int id = t + 256 * it;
        int i = id >> 6, j = id & 63;
        if (i < j) {
            float a = 0.5f * (A[i][j] + A[j][i]);
            A[i][j] = a; A[j][i] = a;
            amax = fmaxf(amax, fabsf(a));
        } else if (i == j) {
            amax = fmaxf(amax, fabsf(A[i][j]));
        }
        V[i][j] = (i == j) ? 1.f : 0.f;
    }
    #pragma unroll
    for (int off = 16; off; off >>= 1) amax = fmaxf(amax, __shfl_xor_sync(0xffffffffu, amax, off));
    if (lane == 0) wred[warp] = amax;
    __syncthreads();
    if (t == 0) {
        float m = wred[0];
        for (int i = 1; i < 8; ++i) m = fmaxf(m, wred[i]);
        anorm_s = m;
        conv_s = 0;
    }
    __syncthreads();
    const float convtol = 1e-6f * anorm_s + 1e-30f;

    for (int sweep = 0; sweep < MAXSWEEPS; ++sweep) {
        float swmax = 0.f;   // only meaningful on warp 0
        for (int r = 0; r < 63; ++r) {
            // generation (warp 0)
            if (warp == 0) {
                int p, q; pairpq(r, lane, p, q);
                float app = A[p][p], aqq = A[q][q], apq = A[p][q];
                swmax = fmaxf(swmax, fabsf(apq));
                float c = 1.f, s = 0.f;
                float thr = 1e-7f * (fabsf(app) + fabsf(aqq)) + 1e-12f;
                if (fabsf(apq) > thr) {
                    float tau = (aqq - app) / (2.f * apq);
                    float tt = copysignf(1.f, tau) / (fabsf(tau) + sqrtf(1.f + tau * tau));
                    c = rsqrtf(1.f + tt * tt);
                    s = tt * c;
                }
                cs[lane] = c; sn[lane] = s;
            }
            __syncthreads();
            // column phase: A <- A*J ; V <- V*J   (warp-uniform per pair, conflict-free)
            #pragma unroll
            for (int j = 0; j < 4; ++j) {
                int k = (warp << 2) | j;
                float s = sn[k];
                if (s != 0.f) {
                    float c = cs[k];
                    int p, q; pairpq(r, k, p, q);
                    #pragma unroll
                    for (int h = 0; h < 2; ++h) {
                        int i = lane + (h << 5);
                        float a0 = A[i][p], a1 = A[i][q];
                        A[i][p] = c * a0 - s * a1;
                        A[i][q] = s * a0 + c * a1;
                        float v0 = V[i][p], v1 = V[i][q];
                        V[i][p] = c * v0 - s * v1;
                        V[i][q] = s * v0 + c * v1;
                    }
                }
            }
            __syncthreads();
            // row phase: A <- J^T * A
            #pragma unroll
            for (int j = 0; j < 4; ++j) {
                int k = (warp << 2) | j;
                float s = sn[k];
                if (s != 0.f) {
                    float c = cs[k];
                    int p, q; pairpq(r, k, p, q);
                    #pragma unroll
                    for (int h = 0; h < 2; ++h) {
                        int jc = lane + (h << 5);
                        float a0 = A[p][jc], a1 = A[q][jc];
                        A[p][jc] = c * a0 - s * a1;
                        A[q][jc] = s * a0 + c * a1;
                    }
                }
            }
            __syncthreads();
        }
        // convergence check
        if (warp == 0) {
            #pragma unroll
            for (int off = 16; off; off >>= 1) swmax = fmaxf(swmax, __shfl_xor_sync(0xffffffffu, swmax, off));
            if (lane == 0) conv_s = (swmax < convtol) ? 1 : 0;
        }
        __syncthreads();
        if (conv_s) break;
    }

    // eigenvalues -> f(lambda)
    if (t < 64) fv[t] = logf(fmaxf(A[t][t], 1e-4f));
    __syncthreads();
    // A := V * diag(f)
    #pragma unroll
    for (int it = 0; it < 16; ++it) {
        int id = t + 256 * it;
        int i = id >> 6, m = id & 63;
        A[i][m] = V[i][m] * fv[m];
    }
    __syncthreads();
    // L[i][j] = sum_m A[i][m] * V[j][m]; each thread: 1 row x 16-col chunk
    const int i0 = t >> 2;
    const int j0 = (t & 3) << 4;
    float acc[16];
    #pragma unroll
    for (int jj = 0; jj < 16; ++jj) acc[jj] = 0.f;
    #pragma unroll
    for (int m = 0; m < 64; ++m) {
        float a = A[i0][m];
        #pragma unroll
        for (int jj = 0; jj < 16; ++jj) acc[jj] += a * V[j0 + jj][m];
    }
    float lsum = 0.f, lsq = 0.f;
    float* dst = g_lbuf + (size_t)b * 4096;
    #pragma unroll
    for (int jj = 0; jj < 16; ++jj) {
        float v = acc[jj];
        dst[i0 * 64 + j0 + jj] = v;
        lsum += v; lsq += v * v;
    }
    #pragma unroll
    for (int off = 16; off; off >>= 1) {
        lsum += __shfl_down_sync(0xffffffffu, lsum, off);
        lsq  += __shfl_down_sync(0xffffffffu, lsq, off);
    }
    if (lane == 0) { wred[warp] = lsum; wred[8 + warp] = lsq; }
    __syncthreads();
    if (t == 0) {
        float s1 = 0.f, s2 = 0.f;
        for (int i = 0; i < 8; ++i) { s1 += wred[i]; s2 += wred[8 + i]; }
        g_eusum[b] = s1;
        g_eusq[b]  = s2;
    }
}

// ---------------- K2: block 1  (matnorm(eu) @ w2 -> relu -> @w3 + eu) ----------------
__global__ __launch_bounds__(128) void dense1_kernel(const float* __restrict__ w2, const float* __restrict__ b2,
                                                     const float* __restrict__ w3, const float* __restrict__ b3) {
    const int t = threadIdx.x;
    const int n = blockIdx.y;
    const int pos = blockIdx.x * 128 + t;
    __shared__ float sw2[1024], sw3[1024], sb2[32], sb3[32];
    __shared__ float meanS[22], isdS[22], em3S[10];
    __shared__ float acc1[32], acc2[32];
    for (int i = t; i < 1024; i += 128) { sw2[i] = w2[i]; sw3[i] = w3[i]; }
    if (t < 32) { sb2[t] = b2[t]; sb3[t] = b3[t]; acc1[t] = 0.f; acc2[t] = 0.f; }
    if (t < 22) {
        float mu = g_eusum[n * 22 + t] * (1.f / 4096.f);
        float var = fmaxf(g_eusq[n * 22 + t] * (1.f / 4096.f) - mu * mu, 0.f);
        meanS[t] = mu;
        isdS[t] = 1.f / fmaxf(sqrtf(var), 1e-3f);   // matnorm: clamp OUTSIDE sqrt
    }
    if (t < 10) em3S[t] = g_em3[t];
    __syncthreads();

    float eu[32];
    #pragma unroll
    for (int c = 0; c < 22; ++c) eu[c] = g_lbuf[((size_t)n * 22 + c) * 4096 + pos];
    #pragma unroll
    for (int c = 22; c < 32; ++c) eu[c] = em3S[c - 22];
    float mt[22];
    #pragma unroll
    for (int c = 0; c < 22; ++c) mt[c] = (eu[c] - meanS[c]) * isdS[c];
    // matnorm of the constant embedding channels is exactly 0 (std clamped), so skip c>=22
    float res[32];
    #pragma unroll
    for (int o = 0; o < 32; ++o) {
        float a = sb2[o];
        #pragma unroll
        for (int c = 0; c < 22; ++c) a += mt[c] * sw2[c * 32 + o];
        res[o] = fmaxf(a, 0.f);
    }
    #pragma unroll
    for (int o = 0; o < 32; ++o) {
        float a = sb3[o];
        #pragma unroll
        for (int c = 0; c < 32; ++c) a += res[c] * sw3[c * 32 + o];
        float h = eu[o] + a;
        g_h2[((size_t)n * 32 + o) * 4096 + pos] = h;
        float s1 = h, s2 = h * h;
        #pragma unroll
        for (int off = 16; off; off >>= 1) {
            s1 += __shfl_down_sync(0xffffffffu, s1, off);
            s2 += __shfl_down_sync(0xffffffffu, s2, off);
        }
        if ((t & 31) == 0) { atomicAdd(&acc1[o], s1); atomicAdd(&acc2[o], s2); }
    }
    __syncthreads();
    if (t < 32) {
        atomicAdd(&g_h2sum[n * 32 + t], acc1[t]);
        atomicAdd(&g_h2sq[n * 32 + t], acc2[t]);
    }
}

// ---------------- K3: block 2  (matnorm(h2) @ w4 -> relu -> @w5 + h2, mean) ----------------
__global__ __launch_bounds__(128) void dense2_kernel(const float* __restrict__ w4, const float* __restrict__ b4,
                                                     const float* __restrict__ w5, const float* __restrict__ b5) {
    const int t = threadIdx.x;
    const int n = blockIdx.y;
    const int pos = blockIdx.x * 128 + t;
    __shared__ float sw4[1024], sw5[1024], sb4[32], sb5[32];
    __shared__ float meanS[32], isdS[32];
    __shared__ float acc1[32];
    for (int i = t; i < 1024; i += 128) { sw4[i] = w4[i]; sw5[i] = w5[i]; }
    if (t < 32) {
        sb4[t] = b4[t]; sb5[t] = b5[t]; acc1[t] = 0.f;
        float mu = g_h2sum[n * 32 + t] * (1.f / 4096.f);
        float var = fmaxf(g_h2sq[n * 32 + t] * (1.f / 4096.f) - mu * mu, 0.f);
        meanS[t] = mu;
        isdS[t] = 1.f / fmaxf(sqrtf(var), 1e-3f);
    }
    __syncthreads();

    float hv[32];
    #pragma unroll
    for (int c = 0; c < 32; ++c) hv[c] = g_h2[((size_t)n * 32 + c) * 4096 + pos];
    float mt[32];
    #pragma unroll
    for (int c = 0; c < 32; ++c) mt[c] = (hv[c] - meanS[c]) * isdS[c];
    float res[32];
    #pragma unroll
    for (int o = 0; o < 32; ++o) {
        float a = sb4[o];
        #pragma unroll
        for (int c = 0; c < 32; ++c) a += mt[c] * sw4[c * 32 + o];
        res[o] = fmaxf(a, 0.f);
    }
    #pragma unroll
    for (int o = 0; o < 32; ++o) {
        float a = sb5[o];
        #pragma unroll
        for (int c = 0; c < 32; ++c) a += res[c] * sw5[c * 32 + o];
        float h = hv[o] + a;
        float s1 = h;
        #pragma unroll
        for (int off = 16; off; off >>= 1) s1 += __shfl_down_sync(0xffffffffu, s1, off);
        if ((t & 31) == 0) atomicAdd(&acc1[o], s1);
    }
    __syncthreads();
    if (t < 32) atomicAdd(&g_cov3[n * 32 + t], acc1[t]);
}

// ---------------- K4: head (cov3 @ w -> softmax) ----------------
__global__ void head_kernel(const float* __restrict__ w, float* __restrict__ out) {
    const int n = threadIdx.x;  // 256 threads
    float c[32];
    #pragma unroll
    for (int ch = 0; ch < 32; ++ch) c[ch] = g_cov3[n * 32 + ch] * (1.f / 4096.f);
    float lg[7];
    #pragma unroll
    for (int cls = 0; cls < 7; ++cls) {
        float a = 0.f;
        #pragma unroll
        for (int ch = 0; ch < 32; ++ch) a += c[ch] * w[ch * 7 + cls];
        lg[cls] = a;
    }
    float mx = lg[0];
    #pragma unroll
    for (int cls = 1; cls < 7; ++cls) mx = fmaxf(mx, lg[cls]);
    float sum = 0.f;
    #pragma unroll
    for (int cls = 0; cls < 7; ++cls) { lg[cls] = expf(lg[cls] - mx); sum += lg[cls]; }
    float inv = 1.f / sum;
    #pragma unroll
    for (int cls = 0; cls < 7; ++cls) out[n * 7 + cls] = lg[cls] * inv;
}

// ---------------- launch ----------------
extern "C" void kernel_launch(void* const* d_in, const int* in_sizes, int n_in,
                              void* d_out, int out_size) {
    const float* x   = (const float*)d_in[0];
    const void*  M   = d_in[1];
    const float* w   = (const float*)d_in[2];
    const float* w2  = (const float*)d_in[3];
    const float* b2  = (const float*)d_in[4];
    const float* w3  = (const float*)d_in[5];
    const float* b3  = (const float*)d_in[6];
    const float* w4  = (const float*)d_in[7];
    const float* b4  = (const float*)d_in[8];
    const float* w5  = (const float*)d_in[9];
    const float* b5  = (const float*)d_in[10];
    const float* we1 = (const float*)d_in[11];
    const float* be1 = (const float*)d_in[12];
    const float* we2 = (const float*)d_in[13];
    const float* be2 = (const float*)d_in[14];
    const float* we3 = (const float*)d_in[15];
    const float* be3 = (const float*)d_in[16];
    const float* lng = (const float*)d_in[17];
    const float* lnb = (const float*)d_in[18];

    init_kernel<<<1, 256>>>(M, we1, be1, we2, be2, we3, be3, lng, lnb);
    eig_kernel<<<256 * 22, 256>>>(x);
    dense1_kernel<<<dim3(32, 256), 128>>>(w2, b2, w3, b3);
    dense2_kernel<<<dim3(32, 256), 128>>>(w4, b4, w5, b5);
    head_kernel<<<1, 256>>>(w, (float*)d_out);
}